// round 1
// baseline (speedup 1.0000x reference)
#include <cuda_runtime.h>
#include <math.h>

// Problem constants
constexpr int Bz  = 4;
constexpr int Sq  = 1024;
constexpr int DIM = 4096;
constexpr int Hh  = 32;
constexpr int HD  = 128;
constexpr int MM  = Bz * Sq;        // 4096 rows
constexpr float QSCALE = 0.08838834764831845f;  // 1/sqrt(128)

// Scratch (static device globals — allocation-free per harness rules)
__device__ float g_xq[MM * DIM];
__device__ float g_xk[MM * DIM];
__device__ float g_xv[MM * DIM];
__device__ float g_att[MM * DIM];

// ---------------------------------------------------------------------------
// SGEMM NT: C[4096,4096] = A[4096,4096] * W[4096,4096]^T  (both K-major)
// 128x128 tile, BK=8, 256 threads, 8x8 per thread, double-buffered smem.
// ---------------------------------------------------------------------------
__global__ __launch_bounds__(256, 2)
void sgemm_nt_kernel(const float* __restrict__ A,
                     const float* __restrict__ W,
                     float* __restrict__ C)
{
    constexpr int K = DIM;
    constexpr int N = DIM;
    constexpr int BK = 8;

    __shared__ float As[2][BK][128];
    __shared__ float Bs[2][BK][128];

    const int tid = threadIdx.x;
    const int bx = blockIdx.x;   // N tile
    const int by = blockIdx.y;   // M tile

    const int lrow = tid >> 1;          // 0..127
    const int lcol = (tid & 1) * 4;     // 0 or 4
    const float* Aptr = A + (by * 128 + lrow) * K + lcol;
    const float* Wptr = W + (bx * 128 + lrow) * K + lcol;

    const int tx = tid & 15;
    const int ty = tid >> 4;

    float acc[8][8];
#pragma unroll
    for (int i = 0; i < 8; i++)
#pragma unroll
        for (int j = 0; j < 8; j++) acc[i][j] = 0.f;

    // prefetch tile 0
    float4 a4 = *(const float4*)Aptr;
    float4 b4 = *(const float4*)Wptr;
    As[0][lcol + 0][lrow] = a4.x; As[0][lcol + 1][lrow] = a4.y;
    As[0][lcol + 2][lrow] = a4.z; As[0][lcol + 3][lrow] = a4.w;
    Bs[0][lcol + 0][lrow] = b4.x; Bs[0][lcol + 1][lrow] = b4.y;
    Bs[0][lcol + 2][lrow] = b4.z; Bs[0][lcol + 3][lrow] = b4.w;
    __syncthreads();

    const int ntiles = K / BK;  // 512
    for (int t = 0; t < ntiles; ++t) {
        const int buf = t & 1;
        if (t + 1 < ntiles) {
            a4 = *(const float4*)(Aptr + (t + 1) * BK);
            b4 = *(const float4*)(Wptr + (t + 1) * BK);
        }
#pragma unroll
        for (int k = 0; k < BK; k++) {
            float ra[8], rb[8];
#pragma unroll
            for (int i = 0; i < 4; i++) {
                ra[i]     = As[buf][k][ty * 4 + i];
                ra[4 + i] = As[buf][k][64 + ty * 4 + i];
                rb[i]     = Bs[buf][k][tx * 4 + i];
                rb[4 + i] = Bs[buf][k][64 + tx * 4 + i];
            }
#pragma unroll
            for (int i = 0; i < 8; i++)
#pragma unroll
                for (int j = 0; j < 8; j++)
                    acc[i][j] += ra[i] * rb[j];
        }
        if (t + 1 < ntiles) {
            const int nb = buf ^ 1;
            As[nb][lcol + 0][lrow] = a4.x; As[nb][lcol + 1][lrow] = a4.y;
            As[nb][lcol + 2][lrow] = a4.z; As[nb][lcol + 3][lrow] = a4.w;
            Bs[nb][lcol + 0][lrow] = b4.x; Bs[nb][lcol + 1][lrow] = b4.y;
            Bs[nb][lcol + 2][lrow] = b4.z; Bs[nb][lcol + 3][lrow] = b4.w;
            __syncthreads();
        }
    }

#pragma unroll
    for (int i = 0; i < 8; i++) {
        const int r = by * 128 + ((i < 4) ? (ty * 4 + i) : (64 + ty * 4 + (i - 4)));
        float4 v0 = make_float4(acc[i][0], acc[i][1], acc[i][2], acc[i][3]);
        float4 v1 = make_float4(acc[i][4], acc[i][5], acc[i][6], acc[i][7]);
        *(float4*)(C + r * N + bx * 128 + tx * 4)      = v0;
        *(float4*)(C + r * N + bx * 128 + 64 + tx * 4) = v1;
    }
}

// ---------------------------------------------------------------------------
// RoPE on q (with 1/sqrt(HD) folded in) and k, in place. One thread per pair.
// Layout per row (b*S+s): h*128 + d, pair p -> elements 2p, 2p+1 within head.
// Flattened: within-row pair index pr in [0, 2048); element offset = 2*pr.
// ---------------------------------------------------------------------------
__global__ __launch_bounds__(256)
void rope_kernel(float* __restrict__ q, float* __restrict__ k,
                 const float* __restrict__ fcos, const float* __restrict__ fsin)
{
    const int idx = blockIdx.x * blockDim.x + threadIdx.x;   // pair index
    constexpr int PAIRS_PER_ROW = DIM / 2;                    // 2048
    const int row = idx / PAIRS_PER_ROW;
    const int pr  = idx - row * PAIRS_PER_ROW;
    const int s = row & (Sq - 1);
    const int p = pr & 63;                                    // within-head pair
    const float c  = fcos[s * 64 + p];
    const float sn = fsin[s * 64 + p];
    const int off = row * DIM + 2 * pr;

    float2 qa = *(float2*)(q + off);
    float2 qo;
    qo.x = (qa.x * c - qa.y * sn) * QSCALE;
    qo.y = (qa.x * sn + qa.y * c) * QSCALE;
    *(float2*)(q + off) = qo;

    float2 ka = *(float2*)(k + off);
    float2 ko;
    ko.x = ka.x * c - ka.y * sn;
    ko.y = ka.x * sn + ka.y * c;
    *(float2*)(k + off) = ko;
}

// ---------------------------------------------------------------------------
// Flash attention, fp32, causal. Grid: (S/64 q-blocks, B*H). 256 threads.
// Per CTA: Q block 64x128 smem, iterate kv-blocks of 64; online softmax.
// Thread layout: tx = tid&15 (col group), ty = tid>>4 (row group).
// Score tile per thread: rows ty*4+i (i<4), cols tx+16*j (j<4).
// O tile per thread:     rows ty*4+i (i<4), cols tx+16*j (j<8).
// ---------------------------------------------------------------------------
__global__ __launch_bounds__(256)
void attn_kernel(const float* __restrict__ Qg, const float* __restrict__ Kg,
                 const float* __restrict__ Vg, float* __restrict__ Og)
{
    extern __shared__ float sm[];
    float* Qs = sm;                 // [64][129]
    float* Ks = Qs + 64 * 129;      // [64][129]
    float* Vs = Ks + 64 * 129;      // [64][129]
    float* Ps = Vs + 64 * 129;      // [64][65]

    const int tid = threadIdx.x;
    const int tx = tid & 15;
    const int ty = tid >> 4;
    const int qb = blockIdx.x;      // 0..15
    const int bh = blockIdx.y;      // 0..127
    const int b  = bh >> 5;
    const int h  = bh & (Hh - 1);

    const int rowbase = b * Sq + qb * 64;
    const float* Qbase = Qg + rowbase * DIM + h * HD;

    // load Q tile (64 x 128) coalesced float4, scalar STS (stride 129)
    for (int idx = tid; idx < 64 * 32; idx += 256) {
        const int r  = idx >> 5;
        const int c4 = (idx & 31) << 2;
        float4 v = *(const float4*)(Qbase + r * DIM + c4);
        float* d = Qs + r * 129 + c4;
        d[0] = v.x; d[1] = v.y; d[2] = v.z; d[3] = v.w;
    }

    float o[4][8];
#pragma unroll
    for (int i = 0; i < 4; i++)
#pragma unroll
        for (int j = 0; j < 8; j++) o[i][j] = 0.f;
    float mrow[4] = {-1e30f, -1e30f, -1e30f, -1e30f};
    float lrow[4] = {0.f, 0.f, 0.f, 0.f};

    const int nkb = qb + 1;
    for (int kb = 0; kb < nkb; ++kb) {
        __syncthreads();  // previous O-phase done with Ks/Vs/Ps; Q visible on iter 0

        const float* Kb = Kg + (b * Sq + kb * 64) * DIM + h * HD;
        const float* Vb = Vg + (b * Sq + kb * 64) * DIM + h * HD;
        for (int idx = tid; idx < 64 * 32; idx += 256) {
            const int r  = idx >> 5;
            const int c4 = (idx & 31) << 2;
            float4 kv = *(const float4*)(Kb + r * DIM + c4);
            float4 vv = *(const float4*)(Vb + r * DIM + c4);
            float* dk = Ks + r * 129 + c4;
            dk[0] = kv.x; dk[1] = kv.y; dk[2] = kv.z; dk[3] = kv.w;
            float* dv = Vs + r * 129 + c4;
            dv[0] = vv.x; dv[1] = vv.y; dv[2] = vv.z; dv[3] = vv.w;
        }
        __syncthreads();

        // S = Q * K^T (64x64), per-thread 4x4
        float sc[4][4];
#pragma unroll
        for (int i = 0; i < 4; i++)
#pragma unroll
            for (int j = 0; j < 4; j++) sc[i][j] = 0.f;

#pragma unroll 4
        for (int k = 0; k < HD; k++) {
            float qv[4], kv[4];
#pragma unroll
            for (int i = 0; i < 4; i++) qv[i] = Qs[(ty * 4 + i) * 129 + k];
#pragma unroll
            for (int j = 0; j < 4; j++) kv[j] = Ks[(tx + 16 * j) * 129 + k];
#pragma unroll
            for (int i = 0; i < 4; i++)
#pragma unroll
                for (int j = 0; j < 4; j++)
                    sc[i][j] += qv[i] * kv[j];
        }

        // causal mask (only diagonal block needs it)
        if (kb == qb) {
#pragma unroll
            for (int i = 0; i < 4; i++) {
                const int gr = ty * 4 + i;
#pragma unroll
                for (int j = 0; j < 4; j++) {
                    const int gc = tx + 16 * j;
                    if (gc > gr) sc[i][j] = -1e30f;
                }
            }
        }

        // online softmax update per row; reductions across the 16 tx lanes
#pragma unroll
        for (int i = 0; i < 4; i++) {
            float rm = fmaxf(fmaxf(sc[i][0], sc[i][1]), fmaxf(sc[i][2], sc[i][3]));
#pragma unroll
            for (int off = 8; off >= 1; off >>= 1)
                rm = fmaxf(rm, __shfl_xor_sync(0xffffffffu, rm, off));
            const float mnew  = fmaxf(mrow[i], rm);
            const float scale = __expf(mrow[i] - mnew);
            float rs = 0.f;
#pragma unroll
            for (int j = 0; j < 4; j++) {
                sc[i][j] = __expf(sc[i][j] - mnew);
                rs += sc[i][j];
            }
#pragma unroll
            for (int off = 8; off >= 1; off >>= 1)
                rs += __shfl_xor_sync(0xffffffffu, rs, off);
            lrow[i] = lrow[i] * scale + rs;
            mrow[i] = mnew;
#pragma unroll
            for (int j = 0; j < 8; j++) o[i][j] *= scale;
#pragma unroll
            for (int j = 0; j < 4; j++)
                Ps[(ty * 4 + i) * 65 + tx + 16 * j] = sc[i][j];
        }
        __syncthreads();

        // O += P * V  (64x128), per-thread 4x8
#pragma unroll 2
        for (int k = 0; k < 64; k++) {
            float pv[4], vv[8];
#pragma unroll
            for (int i = 0; i < 4; i++) pv[i] = Ps[(ty * 4 + i) * 65 + k];
#pragma unroll
            for (int j = 0; j < 8; j++) vv[j] = Vs[k * 129 + tx + 16 * j];
#pragma unroll
            for (int i = 0; i < 4; i++)
#pragma unroll
                for (int j = 0; j < 8; j++)
                    o[i][j] += pv[i] * vv[j];
        }
    }

    // finalize + write
#pragma unroll
    for (int i = 0; i < 4; i++) {
        const float inv = 1.f / lrow[i];
        const int r = rowbase + ty * 4 + i;
#pragma unroll
        for (int j = 0; j < 8; j++)
            Og[r * DIM + h * HD + tx + 16 * j] = o[i][j] * inv;
    }
}

// ---------------------------------------------------------------------------
// Launch: qkv gemms -> rope -> attention -> output gemm
// ---------------------------------------------------------------------------
extern "C" void kernel_launch(void* const* d_in, const int* in_sizes, int n_in,
                              void* d_out, int out_size)
{
    const float* x    = (const float*)d_in[0];
    // d_in[1] = start_pos (== 0), d_in[4] = mask, d_in[9..10] = zero caches: unused
    const float* fcos = (const float*)d_in[2];
    const float* fsin = (const float*)d_in[3];
    const float* wq   = (const float*)d_in[5];
    const float* wk   = (const float*)d_in[6];
    const float* wv   = (const float*)d_in[7];
    const float* wo   = (const float*)d_in[8];
    float* out = (float*)d_out;

    float *xq, *xk, *xv, *att;
    cudaGetSymbolAddress((void**)&xq,  g_xq);
    cudaGetSymbolAddress((void**)&xk,  g_xk);
    cudaGetSymbolAddress((void**)&xv,  g_xv);
    cudaGetSymbolAddress((void**)&att, g_att);

    const dim3 gg(DIM / 128, MM / 128);   // 32 x 32
    sgemm_nt_kernel<<<gg, 256>>>(x, wq, xq);
    sgemm_nt_kernel<<<gg, 256>>>(x, wk, xk);
    sgemm_nt_kernel<<<gg, 256>>>(x, wv, xv);

    const int npairs = MM * (DIM / 2);
    rope_kernel<<<npairs / 256, 256>>>(xq, xk, fcos, fsin);

    const int smem_bytes = (3 * 64 * 129 + 64 * 65) * (int)sizeof(float);  // ~113 KB
    cudaFuncSetAttribute(attn_kernel, cudaFuncAttributeMaxDynamicSharedMemorySize,
                         smem_bytes);
    attn_kernel<<<dim3(Sq / 64, Bz * Hh), 256, smem_bytes>>>(xq, xk, xv, att);

    sgemm_nt_kernel<<<gg, 256>>>(att, wo, out);
}

// round 4
// speedup vs baseline: 2.0044x; 2.0044x over previous
#include <cuda_runtime.h>
#include <cuda_bf16.h>
#include <cstdint>
#include <math.h>

// Problem constants
constexpr int Bz  = 4;
constexpr int Sq  = 1024;
constexpr int DIM = 4096;
constexpr int Hh  = 32;
constexpr int HD  = 128;
constexpr int MM  = Bz * Sq;        // 4096 rows
constexpr float QSCALE = 0.08838834764831845f;  // 1/sqrt(128)

// Scratch (static device globals — allocation-free per harness rules)
__device__ float g_xq[MM * DIM];
__device__ float g_xk[MM * DIM];
__device__ float g_xv[MM * DIM];
__device__ float g_att[MM * DIM];
__device__ __nv_bfloat16 g_ahi[MM * DIM];
__device__ __nv_bfloat16 g_alo[MM * DIM];
__device__ __nv_bfloat16 g_bhi[DIM * DIM];
__device__ __nv_bfloat16 g_blo[DIM * DIM];

// ---------------------------------------------------------------------------
// fp32 -> bf16 hi/lo split conversion.  4 elems per thread.
// ---------------------------------------------------------------------------
__global__ __launch_bounds__(256)
void cvt_hilo(const float* __restrict__ s,
              __nv_bfloat16* __restrict__ hi, __nv_bfloat16* __restrict__ lo)
{
    const long i = ((long)blockIdx.x * 256 + threadIdx.x) * 4;
    float4 v = *(const float4*)(s + i);
    float f[4] = {v.x, v.y, v.z, v.w};
    __nv_bfloat16 h[4], l[4];
#pragma unroll
    for (int j = 0; j < 4; j++) {
        h[j] = __float2bfloat16(f[j]);
        l[j] = __float2bfloat16(f[j] - __bfloat162float(h[j]));
    }
    *(__nv_bfloat162*)(hi + i)     = __halves2bfloat162(h[0], h[1]);
    *(__nv_bfloat162*)(hi + i + 2) = __halves2bfloat162(h[2], h[3]);
    *(__nv_bfloat162*)(lo + i)     = __halves2bfloat162(l[0], l[1]);
    *(__nv_bfloat162*)(lo + i + 2) = __halves2bfloat162(l[2], l[3]);
}

// ---------------------------------------------------------------------------
// Tensor-core GEMM via mma.sync (sm_100-safe, no tcgen05).
// C[4096,4096] = A * B^T, A/B given as bf16 hi/lo pairs, K-major.
// 3-product split: hh + hl + lh.
// CTA tile 128x128, BK=32, 8 warps (2x4), warp tile 64x32.
// 3-stage cp.async pipeline. Smem rows padded to 40 bf16 (80B) -> bank-clean.
// ---------------------------------------------------------------------------
constexpr int BM = 128, BN = 128, BK = 32;
constexpr int KPAD = 40;                       // padded row length (elems)
constexpr int TILE_E  = BM * KPAD;             // 5120 elems per tile
constexpr int STAGE_E = 4 * TILE_E;            // Ahi,Alo,Bhi,Blo
constexpr int STAGES  = 3;
constexpr int GEMM_SMEM = STAGES * STAGE_E * 2;  // bytes (122880)

__device__ __forceinline__ uint32_t smem_u32(const void* p) {
    uint32_t a;
    asm("{ .reg .u64 t; cvta.to.shared.u64 t, %1; cvt.u32.u64 %0, t; }"
        : "=r"(a) : "l"(p));
    return a;
}

#define MMA_BF16(d, a, b)                                                     \
    asm volatile(                                                             \
        "mma.sync.aligned.m16n8k16.row.col.f32.bf16.bf16.f32 "                \
        "{%0,%1,%2,%3}, {%4,%5,%6,%7}, {%8,%9}, {%0,%1,%2,%3};"               \
        : "+f"((d)[0]), "+f"((d)[1]), "+f"((d)[2]), "+f"((d)[3])              \
        : "r"((a)[0]), "r"((a)[1]), "r"((a)[2]), "r"((a)[3]),                 \
          "r"((b)[0]), "r"((b)[1]))

__global__ __launch_bounds__(256, 1)
void tc_gemm(const __nv_bfloat16* __restrict__ Ahi, const __nv_bfloat16* __restrict__ Alo,
             const __nv_bfloat16* __restrict__ Bhi, const __nv_bfloat16* __restrict__ Blo,
             float* __restrict__ C)
{
    extern __shared__ __align__(16) __nv_bfloat16 sb[];

    const int tid  = threadIdx.x;
    const int wid  = tid >> 5;
    const int lane = tid & 31;
    const int g    = lane >> 2;      // groupID 0..7
    const int tig  = lane & 3;       // thread-in-group
    const int warp_m = wid >> 2;     // 0..1
    const int warp_n = wid & 3;      // 0..3

    // L2-friendly rasterization: groups of 8 M-tiles sweep all 32 N-tiles
    const int bid = blockIdx.x;
    const int grp = bid >> 8;
    const int r   = bid & 255;
    const int m0  = (grp * 8 + (r & 7)) * BM;
    const int n0  = (r >> 3) * BN;

    const __nv_bfloat16* srcs[4] = {
        Ahi + (long)m0 * DIM, Alo + (long)m0 * DIM,
        Bhi + (long)n0 * DIM, Blo + (long)n0 * DIM };

    const uint32_t smb = smem_u32(sb);

    // per-thread copy map: chunk c = tid + 256*q (q<2): row=c>>2, colchunk=c&3
    const int cr0 = tid >> 2, cr1 = (tid + 256) >> 2;
    const int cc  = tid & 3;

    auto issue = [&](int kt, int stage) {
        const long kof = (long)kt * BK;
#pragma unroll
        for (int t4 = 0; t4 < 4; t4++) {
            const __nv_bfloat16* s0 = srcs[t4] + (long)cr0 * DIM + kof + cc * 8;
            const __nv_bfloat16* s1 = srcs[t4] + (long)cr1 * DIM + kof + cc * 8;
            const uint32_t d0 = smb + (uint32_t)(stage * STAGE_E + t4 * TILE_E + cr0 * KPAD + cc * 8) * 2;
            const uint32_t d1 = smb + (uint32_t)(stage * STAGE_E + t4 * TILE_E + cr1 * KPAD + cc * 8) * 2;
            asm volatile("cp.async.cg.shared.global [%0], [%1], 16;" :: "r"(d0), "l"(s0));
            asm volatile("cp.async.cg.shared.global [%0], [%1], 16;" :: "r"(d1), "l"(s1));
        }
    };

    float acc[4][4][4];
#pragma unroll
    for (int i = 0; i < 4; i++)
#pragma unroll
        for (int j = 0; j < 4; j++)
#pragma unroll
            for (int q = 0; q < 4; q++) acc[i][j][q] = 0.f;

    // prologue: stages 0,1
    issue(0, 0);
    asm volatile("cp.async.commit_group;" ::: "memory");
    issue(1, 1);
    asm volatile("cp.async.commit_group;" ::: "memory");

    const int NT = DIM / BK;   // 128
    for (int t = 0; t < NT; t++) {
        asm volatile("cp.async.wait_group 1;" ::: "memory");
        __syncthreads();

        if (t + 2 < NT) issue(t + 2, (t + 2) % STAGES);
        asm volatile("cp.async.commit_group;" ::: "memory");

        const int st = t % STAGES;
        const __nv_bfloat16* sAh = sb + st * STAGE_E;
        const __nv_bfloat16* sAl = sAh + TILE_E;
        const __nv_bfloat16* sBh = sAl + TILE_E;
        const __nv_bfloat16* sBl = sBh + TILE_E;

#pragma unroll
        for (int ks = 0; ks < 2; ks++) {
            const int kk = ks * 16;
            uint32_t ah[4][4], al[4][4], bh[4][2], bl[4][2];
#pragma unroll
            for (int mf = 0; mf < 4; mf++) {
                const int r0 = warp_m * 64 + mf * 16 + g;
                const int c0 = kk + tig * 2;
                ah[mf][0] = *(const uint32_t*)(sAh + r0 * KPAD + c0);
                ah[mf][1] = *(const uint32_t*)(sAh + (r0 + 8) * KPAD + c0);
                ah[mf][2] = *(const uint32_t*)(sAh + r0 * KPAD + c0 + 8);
                ah[mf][3] = *(const uint32_t*)(sAh + (r0 + 8) * KPAD + c0 + 8);
                al[mf][0] = *(const uint32_t*)(sAl + r0 * KPAD + c0);
                al[mf][1] = *(const uint32_t*)(sAl + (r0 + 8) * KPAD + c0);
                al[mf][2] = *(const uint32_t*)(sAl + r0 * KPAD + c0 + 8);
                al[mf][3] = *(const uint32_t*)(sAl + (r0 + 8) * KPAD + c0 + 8);
            }
#pragma unroll
            for (int nf = 0; nf < 4; nf++) {
                const int nrow = warp_n * 32 + nf * 8 + g;
                const int c0 = kk + tig * 2;
                bh[nf][0] = *(const uint32_t*)(sBh + nrow * KPAD + c0);
                bh[nf][1] = *(const uint32_t*)(sBh + nrow * KPAD + c0 + 8);
                bl[nf][0] = *(const uint32_t*)(sBl + nrow * KPAD + c0);
                bl[nf][1] = *(const uint32_t*)(sBl + nrow * KPAD + c0 + 8);
            }
#pragma unroll
            for (int mf = 0; mf < 4; mf++)
#pragma unroll
                for (int nf = 0; nf < 4; nf++) {
                    MMA_BF16(acc[mf][nf], ah[mf], bh[nf]);
                    MMA_BF16(acc[mf][nf], ah[mf], bl[nf]);
                    MMA_BF16(acc[mf][nf], al[mf], bh[nf]);
                }
        }
        __syncthreads();
    }

    // epilogue: direct store
#pragma unroll
    for (int mf = 0; mf < 4; mf++) {
        const long gr0 = m0 + warp_m * 64 + mf * 16 + g;
#pragma unroll
        for (int nf = 0; nf < 4; nf++) {
            const int gc = n0 + warp_n * 32 + nf * 8 + tig * 2;
            *(float2*)(C + gr0 * DIM + gc)       = make_float2(acc[mf][nf][0], acc[mf][nf][1]);
            *(float2*)(C + (gr0 + 8) * DIM + gc) = make_float2(acc[mf][nf][2], acc[mf][nf][3]);
        }
    }
}

// ---------------------------------------------------------------------------
// RoPE on q (with 1/sqrt(HD) folded in) and k, in place.
// ---------------------------------------------------------------------------
__global__ __launch_bounds__(256)
void rope_kernel(float* __restrict__ q, float* __restrict__ k,
                 const float* __restrict__ fcos, const float* __restrict__ fsin)
{
    const int idx = blockIdx.x * blockDim.x + threadIdx.x;   // pair index
    constexpr int PAIRS_PER_ROW = DIM / 2;                    // 2048
    const int row = idx / PAIRS_PER_ROW;
    const int pr  = idx - row * PAIRS_PER_ROW;
    const int s = row & (Sq - 1);
    const int p = pr & 63;                                    // within-head pair
    const float c  = fcos[s * 64 + p];
    const float sn = fsin[s * 64 + p];
    const int off = row * DIM + 2 * pr;

    float2 qa = *(float2*)(q + off);
    float2 qo;
    qo.x = (qa.x * c - qa.y * sn) * QSCALE;
    qo.y = (qa.x * sn + qa.y * c) * QSCALE;
    *(float2*)(q + off) = qo;

    float2 ka = *(float2*)(k + off);
    float2 ko;
    ko.x = ka.x * c - ka.y * sn;
    ko.y = ka.x * sn + ka.y * c;
    *(float2*)(k + off) = ko;
}

// ---------------------------------------------------------------------------
// Flash attention, fp32, causal. Grid: (S/64 q-blocks, B*H). 256 threads.
// ---------------------------------------------------------------------------
__global__ __launch_bounds__(256)
void attn_kernel(const float* __restrict__ Qg, const float* __restrict__ Kg,
                 const float* __restrict__ Vg, float* __restrict__ Og)
{
    extern __shared__ float smf[];
    float* Qs = smf;                // [64][129]
    float* Ks = Qs + 64 * 129;      // [64][129]
    float* Vs = Ks + 64 * 129;      // [64][129]
    float* Ps = Vs + 64 * 129;      // [64][65]

    const int tid = threadIdx.x;
    const int tx = tid & 15;
    const int ty = tid >> 4;
    const int qb = blockIdx.x;      // 0..15
    const int bh = blockIdx.y;      // 0..127
    const int b  = bh >> 5;
    const int h  = bh & (Hh - 1);

    const int rowbase = b * Sq + qb * 64;
    const float* Qbase = Qg + (long)rowbase * DIM + h * HD;

    for (int idx = tid; idx < 64 * 32; idx += 256) {
        const int r  = idx >> 5;
        const int c4 = (idx & 31) << 2;
        float4 v = *(const float4*)(Qbase + (long)r * DIM + c4);
        float* d = Qs + r * 129 + c4;
        d[0] = v.x; d[1] = v.y; d[2] = v.z; d[3] = v.w;
    }

    float o[4][8];
#pragma unroll
    for (int i = 0; i < 4; i++)
#pragma unroll
        for (int j = 0; j < 8; j++) o[i][j] = 0.f;
    float mrow[4] = {-1e30f, -1e30f, -1e30f, -1e30f};
    float lrow[4] = {0.f, 0.f, 0.f, 0.f};

    const int nkb = qb + 1;
    for (int kb = 0; kb < nkb; ++kb) {
        __syncthreads();

        const float* Kb = Kg + (long)(b * Sq + kb * 64) * DIM + h * HD;
        const float* Vb = Vg + (long)(b * Sq + kb * 64) * DIM + h * HD;
        for (int idx = tid; idx < 64 * 32; idx += 256) {
            const int r  = idx >> 5;
            const int c4 = (idx & 31) << 2;
            float4 kv = *(const float4*)(Kb + (long)r * DIM + c4);
            float4 vv = *(const float4*)(Vb + (long)r * DIM + c4);
            float* dk = Ks + r * 129 + c4;
            dk[0] = kv.x; dk[1] = kv.y; dk[2] = kv.z; dk[3] = kv.w;
            float* dv = Vs + r * 129 + c4;
            dv[0] = vv.x; dv[1] = vv.y; dv[2] = vv.z; dv[3] = vv.w;
        }
        __syncthreads();

        float sc[4][4];
#pragma unroll
        for (int i = 0; i < 4; i++)
#pragma unroll
            for (int j = 0; j < 4; j++) sc[i][j] = 0.f;

#pragma unroll 4
        for (int k = 0; k < HD; k++) {
            float qv[4], kv[4];
#pragma unroll
            for (int i = 0; i < 4; i++) qv[i] = Qs[(ty * 4 + i) * 129 + k];
#pragma unroll
            for (int j = 0; j < 4; j++) kv[j] = Ks[(tx + 16 * j) * 129 + k];
#pragma unroll
            for (int i = 0; i < 4; i++)
#pragma unroll
                for (int j = 0; j < 4; j++)
                    sc[i][j] += qv[i] * kv[j];
        }

        if (kb == qb) {
#pragma unroll
            for (int i = 0; i < 4; i++) {
                const int gr = ty * 4 + i;
#pragma unroll
                for (int j = 0; j < 4; j++) {
                    const int gc = tx + 16 * j;
                    if (gc > gr) sc[i][j] = -1e30f;
                }
            }
        }

#pragma unroll
        for (int i = 0; i < 4; i++) {
            float rm = fmaxf(fmaxf(sc[i][0], sc[i][1]), fmaxf(sc[i][2], sc[i][3]));
#pragma unroll
            for (int off = 8; off >= 1; off >>= 1)
                rm = fmaxf(rm, __shfl_xor_sync(0xffffffffu, rm, off));
            const float mnew  = fmaxf(mrow[i], rm);
            const float scale = __expf(mrow[i] - mnew);
            float rs = 0.f;
#pragma unroll
            for (int j = 0; j < 4; j++) {
                sc[i][j] = __expf(sc[i][j] - mnew);
                rs += sc[i][j];
            }
#pragma unroll
            for (int off = 8; off >= 1; off >>= 1)
                rs += __shfl_xor_sync(0xffffffffu, rs, off);
            lrow[i] = lrow[i] * scale + rs;
            mrow[i] = mnew;
#pragma unroll
            for (int j = 0; j < 8; j++) o[i][j] *= scale;
#pragma unroll
            for (int j = 0; j < 4; j++)
                Ps[(ty * 4 + i) * 65 + tx + 16 * j] = sc[i][j];
        }
        __syncthreads();

#pragma unroll 2
        for (int k = 0; k < 64; k++) {
            float pv[4], vv[8];
#pragma unroll
            for (int i = 0; i < 4; i++) pv[i] = Ps[(ty * 4 + i) * 65 + k];
#pragma unroll
            for (int j = 0; j < 8; j++) vv[j] = Vs[k * 129 + tx + 16 * j];
#pragma unroll
            for (int i = 0; i < 4; i++)
#pragma unroll
                for (int j = 0; j < 8; j++)
                    o[i][j] += pv[i] * vv[j];
        }
    }

#pragma unroll
    for (int i = 0; i < 4; i++) {
        const float inv = 1.f / lrow[i];
        const long r = rowbase + ty * 4 + i;
#pragma unroll
        for (int j = 0; j < 8; j++)
            Og[r * DIM + h * HD + tx + 16 * j] = o[i][j] * inv;
    }
}

// ---------------------------------------------------------------------------
// Launch
// ---------------------------------------------------------------------------
extern "C" void kernel_launch(void* const* d_in, const int* in_sizes, int n_in,
                              void* d_out, int out_size)
{
    const float* x    = (const float*)d_in[0];
    const float* fcos = (const float*)d_in[2];
    const float* fsin = (const float*)d_in[3];
    const float* wq   = (const float*)d_in[5];
    const float* wk   = (const float*)d_in[6];
    const float* wv   = (const float*)d_in[7];
    const float* wo   = (const float*)d_in[8];
    float* out = (float*)d_out;

    float *xq, *xk, *xv, *att;
    __nv_bfloat16 *ahi, *alo, *bhi, *blo;
    cudaGetSymbolAddress((void**)&xq,  g_xq);
    cudaGetSymbolAddress((void**)&xk,  g_xk);
    cudaGetSymbolAddress((void**)&xv,  g_xv);
    cudaGetSymbolAddress((void**)&att, g_att);
    cudaGetSymbolAddress((void**)&ahi, g_ahi);
    cudaGetSymbolAddress((void**)&alo, g_alo);
    cudaGetSymbolAddress((void**)&bhi, g_bhi);
    cudaGetSymbolAddress((void**)&blo, g_blo);

    cudaFuncSetAttribute(tc_gemm, cudaFuncAttributeMaxDynamicSharedMemorySize, GEMM_SMEM);

    const int cvt_blocks = (MM * DIM) / (256 * 4);   // 16384
    const int gemm_grid  = (MM / 128) * (DIM / 128); // 1024

    // x -> hi/lo once, reused by the 3 projection GEMMs
    cvt_hilo<<<cvt_blocks, 256>>>(x, ahi, alo);

    cvt_hilo<<<cvt_blocks, 256>>>(wq, bhi, blo);
    tc_gemm<<<gemm_grid, 256, GEMM_SMEM>>>(ahi, alo, bhi, blo, xq);
    cvt_hilo<<<cvt_blocks, 256>>>(wk, bhi, blo);
    tc_gemm<<<gemm_grid, 256, GEMM_SMEM>>>(ahi, alo, bhi, blo, xk);
    cvt_hilo<<<cvt_blocks, 256>>>(wv, bhi, blo);
    tc_gemm<<<gemm_grid, 256, GEMM_SMEM>>>(ahi, alo, bhi, blo, xv);

    const int npairs = MM * (DIM / 2);
    rope_kernel<<<npairs / 256, 256>>>(xq, xk, fcos, fsin);

    const int attn_smem = (3 * 64 * 129 + 64 * 65) * (int)sizeof(float);
    cudaFuncSetAttribute(attn_kernel, cudaFuncAttributeMaxDynamicSharedMemorySize, attn_smem);
    attn_kernel<<<dim3(Sq / 64, Bz * Hh), 256, attn_smem>>>(xq, xk, xv, att);

    cvt_hilo<<<cvt_blocks, 256>>>(att, ahi, alo);
    cvt_hilo<<<cvt_blocks, 256>>>(wo, bhi, blo);
    tc_gemm<<<gemm_grid, 256, GEMM_SMEM>>>(ahi, alo, bhi, blo, out);
}

// round 5
// speedup vs baseline: 2.3307x; 1.1628x over previous
#include <cuda_runtime.h>
#include <cuda_bf16.h>
#include <cstdint>
#include <math.h>

// Problem constants
constexpr int Bz  = 4;
constexpr int Sq  = 1024;
constexpr int DIM = 4096;
constexpr int Hh  = 32;
constexpr int HD  = 128;
constexpr int MM  = Bz * Sq;        // 4096 rows
constexpr float QS2 = 0.08838834764831845f * 1.4426950408889634f; // 1/sqrt(128)*log2(e)

// Scratch (static device globals — allocation-free per harness rules)
__device__ float g_xq[MM * DIM];
__device__ float g_xk[MM * DIM];
__device__ float g_xv[MM * DIM];
__device__ __nv_bfloat16 g_ahi[MM * DIM];
__device__ __nv_bfloat16 g_alo[MM * DIM];
__device__ __nv_bfloat16 g_bhi[DIM * DIM];
__device__ __nv_bfloat16 g_blo[DIM * DIM];
__device__ __nv_bfloat16 g_qhi[MM * DIM];
__device__ __nv_bfloat16 g_qlo[MM * DIM];
__device__ __nv_bfloat16 g_khi[MM * DIM];
__device__ __nv_bfloat16 g_klo[MM * DIM];
__device__ __nv_bfloat16 g_vhi[MM * DIM];
__device__ __nv_bfloat16 g_vlo[MM * DIM];

// ---------------------------------------------------------------------------
// helpers
// ---------------------------------------------------------------------------
__device__ __forceinline__ uint32_t smem_u32(const void* p) {
    uint32_t a;
    asm("{ .reg .u64 t; cvta.to.shared.u64 t, %1; cvt.u32.u64 %0, t; }"
        : "=r"(a) : "l"(p));
    return a;
}

__device__ __forceinline__ void ldsm4(uint32_t* r, uint32_t addr) {
    asm volatile("ldmatrix.sync.aligned.m8n8.x4.shared.b16 {%0,%1,%2,%3}, [%4];"
        : "=r"(r[0]), "=r"(r[1]), "=r"(r[2]), "=r"(r[3]) : "r"(addr));
}
__device__ __forceinline__ void ldsm4t(uint32_t* r, uint32_t addr) {
    asm volatile("ldmatrix.sync.aligned.m8n8.x4.trans.shared.b16 {%0,%1,%2,%3}, [%4];"
        : "=r"(r[0]), "=r"(r[1]), "=r"(r[2]), "=r"(r[3]) : "r"(addr));
}
__device__ __forceinline__ void mma16816(float* d, const uint32_t* a,
                                         uint32_t b0, uint32_t b1) {
    asm volatile(
        "mma.sync.aligned.m16n8k16.row.col.f32.bf16.bf16.f32 "
        "{%0,%1,%2,%3}, {%4,%5,%6,%7}, {%8,%9}, {%0,%1,%2,%3};"
        : "+f"(d[0]), "+f"(d[1]), "+f"(d[2]), "+f"(d[3])
        : "r"(a[0]), "r"(a[1]), "r"(a[2]), "r"(a[3]), "r"(b0), "r"(b1));
}
__device__ __forceinline__ float fexp2(float x) {
    float y;
    asm("ex2.approx.ftz.f32 %0, %1;" : "=f"(y) : "f"(x));
    return y;
}

// ---------------------------------------------------------------------------
// fp32 -> bf16 hi/lo split conversion.  4 elems per thread.
// ---------------------------------------------------------------------------
__global__ __launch_bounds__(256)
void cvt_hilo(const float* __restrict__ s,
              __nv_bfloat16* __restrict__ hi, __nv_bfloat16* __restrict__ lo)
{
    const long i = ((long)blockIdx.x * 256 + threadIdx.x) * 4;
    float4 v = *(const float4*)(s + i);
    float f[4] = {v.x, v.y, v.z, v.w};
    __nv_bfloat16 h[4], l[4];
#pragma unroll
    for (int j = 0; j < 4; j++) {
        h[j] = __float2bfloat16(f[j]);
        l[j] = __float2bfloat16(f[j] - __bfloat162float(h[j]));
    }
    *(__nv_bfloat162*)(hi + i)     = __halves2bfloat162(h[0], h[1]);
    *(__nv_bfloat162*)(hi + i + 2) = __halves2bfloat162(h[2], h[3]);
    *(__nv_bfloat162*)(lo + i)     = __halves2bfloat162(l[0], l[1]);
    *(__nv_bfloat162*)(lo + i + 2) = __halves2bfloat162(l[2], l[3]);
}

// ---------------------------------------------------------------------------
// Tensor-core GEMM: C[4096,4096] = A * B^T, hi/lo bf16 split (hh+hl+lh).
// CTA 128x256, BK=32, 8 warps (2m x 4n), warp tile 64x64, ldmatrix.x4,
// 3-stage cp.async. KPAD=40 rows -> bank-conflict-free ldmatrix.
// ---------------------------------------------------------------------------
constexpr int BM = 128, BN = 256, BK = 32, KPAD = 40;
constexpr int A_E = BM * KPAD;                 // 5120 elems per A tile
constexpr int B_E = BN * KPAD;                 // 10240 elems per B tile
constexpr int STAGE_E = 2 * A_E + 2 * B_E;     // 30720
constexpr int STAGES = 3;
constexpr int GEMM_SMEM = STAGES * STAGE_E * 2; // 184320 bytes

__global__ __launch_bounds__(256, 1)
void tc_gemm(const __nv_bfloat16* __restrict__ Ahi, const __nv_bfloat16* __restrict__ Alo,
             const __nv_bfloat16* __restrict__ Bhi, const __nv_bfloat16* __restrict__ Blo,
             float* __restrict__ C)
{
    extern __shared__ __align__(16) __nv_bfloat16 sb[];
    const uint32_t smb = smem_u32(sb);

    const int tid  = threadIdx.x;
    const int wid  = tid >> 5;
    const int lane = tid & 31;
    const int g    = lane >> 2;
    const int tig  = lane & 3;
    const int warp_m = wid & 1;    // 0..1  (64 rows)
    const int warp_n = wid >> 1;   // 0..3  (64 cols)

    // raster: 32 m-tiles x 16 n-tiles, groups of 4 m-tiles
    const int bid = blockIdx.x;
    const int grp = bid >> 6;
    const int r   = bid & 63;
    const int m0  = (grp * 4 + (r & 3)) * BM;
    const int n0  = (r >> 2) * BN;

    const __nv_bfloat16* sAg[2] = { Ahi + (long)m0 * DIM, Alo + (long)m0 * DIM };
    const __nv_bfloat16* sBg[2] = { Bhi + (long)n0 * DIM, Blo + (long)n0 * DIM };

    auto issue = [&](int kt, int st) {
        const long kof = (long)kt * BK;
        const uint32_t sbase = smb + (uint32_t)(st * STAGE_E) * 2;
#pragma unroll
        for (int arr = 0; arr < 2; arr++) {
#pragma unroll
            for (int q = 0; q < 2; q++) {          // A: 512 uint4 per array
                const int c = tid + 256 * q;
                const int row = c >> 2, cc = (c & 3) * 8;
                const __nv_bfloat16* s = sAg[arr] + (long)row * DIM + kof + cc;
                const uint32_t d = sbase + (uint32_t)(arr * A_E + row * KPAD + cc) * 2;
                asm volatile("cp.async.cg.shared.global [%0], [%1], 16;" :: "r"(d), "l"(s));
            }
#pragma unroll
            for (int q = 0; q < 4; q++) {          // B: 1024 uint4 per array
                const int c = tid + 256 * q;
                const int row = c >> 2, cc = (c & 3) * 8;
                const __nv_bfloat16* s = sBg[arr] + (long)row * DIM + kof + cc;
                const uint32_t d = sbase + (uint32_t)(2 * A_E + arr * B_E + row * KPAD + cc) * 2;
                asm volatile("cp.async.cg.shared.global [%0], [%1], 16;" :: "r"(d), "l"(s));
            }
        }
    };

    float acc[4][8][4];
#pragma unroll
    for (int i = 0; i < 4; i++)
#pragma unroll
        for (int j = 0; j < 8; j++)
#pragma unroll
            for (int q = 0; q < 4; q++) acc[i][j][q] = 0.f;

    issue(0, 0);
    asm volatile("cp.async.commit_group;" ::: "memory");
    issue(1, 1);
    asm volatile("cp.async.commit_group;" ::: "memory");

    // invariant parts of ldmatrix lane addressing
    const int arow = warp_m * 64 + (lane & 15);              // A row
    const int acol8 = (lane >> 4) << 3;                       // A col half
    const int brow = warp_n * 64 + (lane & 7) + ((lane >> 4) << 3);  // B row
    const int bcol8 = ((lane >> 3) & 1) << 3;                 // B col half

    const int NT = DIM / BK;   // 128
    for (int t = 0; t < NT; t++) {
        asm volatile("cp.async.wait_group 1;" ::: "memory");
        __syncthreads();

        if (t + 2 < NT) issue(t + 2, (t + 2) % STAGES);
        asm volatile("cp.async.commit_group;" ::: "memory");

        const uint32_t base = smb + (uint32_t)((t % STAGES) * STAGE_E) * 2;

#pragma unroll
        for (int ks = 0; ks < 2; ks++) {
            const int kk = ks * 16;
            uint32_t ah[4][4], al[4][4];
#pragma unroll
            for (int mf = 0; mf < 4; mf++) {
                const uint32_t ad = base + (uint32_t)((arow + mf * 16) * KPAD + kk + acol8) * 2;
                ldsm4(ah[mf], ad);
                ldsm4(al[mf], ad + (uint32_t)A_E * 2);
            }
#pragma unroll
            for (int nfp = 0; nfp < 4; nfp++) {
                uint32_t bh[4], bl[4];
                const uint32_t bd = base + (uint32_t)(2 * A_E + (brow + nfp * 16) * KPAD + kk + bcol8) * 2;
                ldsm4(bh, bd);
                ldsm4(bl, bd + (uint32_t)B_E * 2);
#pragma unroll
                for (int mf = 0; mf < 4; mf++) {
                    mma16816(acc[mf][2 * nfp],     ah[mf], bh[0], bh[1]);
                    mma16816(acc[mf][2 * nfp],     ah[mf], bl[0], bl[1]);
                    mma16816(acc[mf][2 * nfp],     al[mf], bh[0], bh[1]);
                    mma16816(acc[mf][2 * nfp + 1], ah[mf], bh[2], bh[3]);
                    mma16816(acc[mf][2 * nfp + 1], ah[mf], bl[2], bl[3]);
                    mma16816(acc[mf][2 * nfp + 1], al[mf], bh[2], bh[3]);
                }
            }
        }
        __syncthreads();
    }

    // epilogue
#pragma unroll
    for (int mf = 0; mf < 4; mf++) {
        const long gr0 = m0 + warp_m * 64 + mf * 16 + g;
#pragma unroll
        for (int nf = 0; nf < 8; nf++) {
            const int gc = n0 + warp_n * 64 + nf * 8 + tig * 2;
            *(float2*)(C + gr0 * DIM + gc)       = make_float2(acc[mf][nf][0], acc[mf][nf][1]);
            *(float2*)(C + (gr0 + 8) * DIM + gc) = make_float2(acc[mf][nf][2], acc[mf][nf][3]);
        }
    }
}

// ---------------------------------------------------------------------------
// RoPE + hi/lo split:  q (scaled by 1/sqrt(HD)*log2e, rotated), k (rotated),
// v (plain).  Reads fp32 projections, writes bf16 hi/lo pairs.
// ---------------------------------------------------------------------------
__global__ __launch_bounds__(256)
void rope_cvt(const float* __restrict__ q, const float* __restrict__ k,
              const float* __restrict__ v,
              const float* __restrict__ fcos, const float* __restrict__ fsin,
              __nv_bfloat16* __restrict__ qh, __nv_bfloat16* __restrict__ ql,
              __nv_bfloat16* __restrict__ kh, __nv_bfloat16* __restrict__ kl,
              __nv_bfloat16* __restrict__ vh, __nv_bfloat16* __restrict__ vl)
{
    const int idx = blockIdx.x * blockDim.x + threadIdx.x;   // pair index
    constexpr int PAIRS_PER_ROW = DIM / 2;
    const int row = idx / PAIRS_PER_ROW;
    const int pr  = idx - row * PAIRS_PER_ROW;
    const int s = row & (Sq - 1);
    const int p = pr & 63;
    const float c  = fcos[s * 64 + p];
    const float sn = fsin[s * 64 + p];
    const long off = (long)row * DIM + 2 * pr;

    float2 qa = *(const float2*)(q + off);
    float qx = (qa.x * c - qa.y * sn) * QS2;
    float qy = (qa.x * sn + qa.y * c) * QS2;
    __nv_bfloat16 h0 = __float2bfloat16(qx), h1 = __float2bfloat16(qy);
    *(__nv_bfloat162*)(qh + off) = __halves2bfloat162(h0, h1);
    *(__nv_bfloat162*)(ql + off) = __halves2bfloat162(
        __float2bfloat16(qx - __bfloat162float(h0)),
        __float2bfloat16(qy - __bfloat162float(h1)));

    float2 ka = *(const float2*)(k + off);
    float kx = ka.x * c - ka.y * sn;
    float ky = ka.x * sn + ka.y * c;
    h0 = __float2bfloat16(kx); h1 = __float2bfloat16(ky);
    *(__nv_bfloat162*)(kh + off) = __halves2bfloat162(h0, h1);
    *(__nv_bfloat162*)(kl + off) = __halves2bfloat162(
        __float2bfloat16(kx - __bfloat162float(h0)),
        __float2bfloat16(ky - __bfloat162float(h1)));

    float2 va = *(const float2*)(v + off);
    h0 = __float2bfloat16(va.x); h1 = __float2bfloat16(va.y);
    *(__nv_bfloat162*)(vh + off) = __halves2bfloat162(h0, h1);
    *(__nv_bfloat162*)(vl + off) = __halves2bfloat162(
        __float2bfloat16(va.x - __bfloat162float(h0)),
        __float2bfloat16(va.y - __bfloat162float(h1)));
}

// ---------------------------------------------------------------------------
// Flash attention on tensor cores.  Q block 128 rows, KV blocks 64 rows.
// 256 threads (8 warps, 16 q-rows each).  3-product hi/lo for QK and PV.
// exp2-domain softmax (log2e folded into q).  Output written as hi/lo bf16.
// ---------------------------------------------------------------------------
constexpr int QP = 136;   // padded row (128-col tiles)
constexpr int PP = 72;    // padded row (64-col P)
// smem element offsets
constexpr int O_QH = 0;
constexpr int O_QL = O_QH + 128 * QP;
constexpr int O_KH = O_QL + 128 * QP;
constexpr int O_KL = O_KH + 64 * QP;
constexpr int O_VH = O_KL + 64 * QP;
constexpr int O_VL = O_VH + 64 * QP;
constexpr int O_PH = O_VL + 64 * QP;
constexpr int O_PL = O_PH + 128 * PP;
constexpr int ATTN_SMEM = (O_PL + 128 * PP) * 2;   // bytes (176128)

__global__ __launch_bounds__(256, 1)
void attn_mma(const __nv_bfloat16* __restrict__ Qh, const __nv_bfloat16* __restrict__ Ql,
              const __nv_bfloat16* __restrict__ Kh, const __nv_bfloat16* __restrict__ Kl,
              const __nv_bfloat16* __restrict__ Vh, const __nv_bfloat16* __restrict__ Vl,
              __nv_bfloat16* __restrict__ Ohi, __nv_bfloat16* __restrict__ Olo)
{
    extern __shared__ __align__(16) __nv_bfloat16 sb[];
    const uint32_t smb = smem_u32(sb);

    const int tid  = threadIdx.x;
    const int w    = tid >> 5;
    const int lane = tid & 31;
    const int g    = lane >> 2;
    const int tig  = lane & 3;

    const int qb = blockIdx.x;      // 0..7
    const int bh = blockIdx.y;      // 0..127
    const int b  = bh >> 5;
    const int h  = bh & (Hh - 1);
    const int rowbase = b * Sq + qb * 128;
    const long colbase = h * HD;

    // ---- load Q tile (128 x 128) hi/lo into smem ----
    {
        const __nv_bfloat16* srcs[2] = { Qh, Ql };
        const uint32_t dsts[2] = { O_QH, O_QL };
#pragma unroll
        for (int a2 = 0; a2 < 2; a2++)
#pragma unroll
            for (int q = 0; q < 8; q++) {
                const int u = tid + 256 * q;           // 2048 uint4
                const int rr = u >> 4, c8 = (u & 15) * 8;
                uint4 v = *(const uint4*)(srcs[a2] + (long)(rowbase + rr) * DIM + colbase + c8);
                *(uint4*)(sb + dsts[a2] + rr * QP + c8) = v;
            }
    }
    __syncthreads();

    // ---- preload Q fragments (loop-invariant) ----
    uint32_t qfh[8][4], qfl[8][4];
    {
        const int rowQ = w * 16 + (lane & 15);
        const int colH = (lane >> 4) << 3;
#pragma unroll
        for (int ks = 0; ks < 8; ks++) {
            const uint32_t ad = smb + (uint32_t)(O_QH + rowQ * QP + ks * 16 + colH) * 2;
            ldsm4(qfh[ks], ad);
            ldsm4(qfl[ks], ad + (uint32_t)(128 * QP) * 2);
        }
    }

    float o[16][4];
#pragma unroll
    for (int i = 0; i < 16; i++)
#pragma unroll
        for (int q = 0; q < 4; q++) o[i][q] = 0.f;
    float m0 = -1e30f, m1 = -1e30f, l0 = 0.f, l1 = 0.f;

    // invariant lane addressing pieces
    const int browK = (lane & 7) + ((lane >> 4) << 3);        // K/B rows (+nfp*16)
    const int bcol8 = ((lane >> 3) & 1) << 3;                  // K col half
    const int vrow  = (lane & 7) + (((lane >> 3) & 1) << 3);   // V rows (+ks2*16)
    const int vcol8 = (lane >> 4) << 3;                        // V col half (+nfp*16)
    const int prow  = w * 16 + (lane & 15);                    // P rows
    const int pcol8 = (lane >> 4) << 3;

    const int nkb = 2 * qb + 2;
    for (int kb = 0; kb < nkb; kb++) {
        __syncthreads();   // prior PV done with V smem

        // ---- load K/V tiles (64 x 128) hi/lo ----
        {
            const __nv_bfloat16* srcs[4] = { Kh, Kl, Vh, Vl };
            const uint32_t dsts[4] = { O_KH, O_KL, O_VH, O_VL };
            const long rbase = (long)(b * Sq + kb * 64);
#pragma unroll
            for (int a2 = 0; a2 < 4; a2++)
#pragma unroll
                for (int q = 0; q < 4; q++) {
                    const int u = tid + 256 * q;       // 1024 uint4
                    const int rr = u >> 4, c8 = (u & 15) * 8;
                    uint4 v = *(const uint4*)(srcs[a2] + (rbase + rr) * DIM + colbase + c8);
                    *(uint4*)(sb + dsts[a2] + rr * QP + c8) = v;
                }
        }
        __syncthreads();

        // ---- S = Q K^T  (16 x 64 per warp) ----
        float s[8][4];
#pragma unroll
        for (int i = 0; i < 8; i++)
#pragma unroll
            for (int q = 0; q < 4; q++) s[i][q] = 0.f;

#pragma unroll
        for (int ks = 0; ks < 8; ks++) {
#pragma unroll
            for (int nfp = 0; nfp < 4; nfp++) {
                uint32_t bh4[4], bl4[4];
                const uint32_t bd = smb + (uint32_t)(O_KH + (browK + nfp * 16) * QP + ks * 16 + bcol8) * 2;
                ldsm4(bh4, bd);
                ldsm4(bl4, bd + (uint32_t)(64 * QP) * 2);
                mma16816(s[2 * nfp],     qfh[ks], bh4[0], bh4[1]);
                mma16816(s[2 * nfp],     qfh[ks], bl4[0], bl4[1]);
                mma16816(s[2 * nfp],     qfl[ks], bh4[0], bh4[1]);
                mma16816(s[2 * nfp + 1], qfh[ks], bh4[2], bh4[3]);
                mma16816(s[2 * nfp + 1], qfh[ks], bl4[2], bl4[3]);
                mma16816(s[2 * nfp + 1], qfl[ks], bh4[2], bh4[3]);
            }
        }

        // ---- causal mask (only near-diagonal warps/blocks) ----
        const int r0g = qb * 128 + w * 16 + g;
        if (kb * 64 + 63 > r0g) {
            const int r1g = r0g + 8;
#pragma unroll
            for (int nf = 0; nf < 8; nf++) {
                const int c0 = kb * 64 + nf * 8 + tig * 2;
                if (c0 > r0g)     s[nf][0] = -1e30f;
                if (c0 + 1 > r0g) s[nf][1] = -1e30f;
                if (c0 > r1g)     s[nf][2] = -1e30f;
                if (c0 + 1 > r1g) s[nf][3] = -1e30f;
            }
        }

        // ---- online softmax (base-2) ----
        float rm0 = -1e30f, rm1 = -1e30f;
#pragma unroll
        for (int nf = 0; nf < 8; nf++) {
            rm0 = fmaxf(rm0, fmaxf(s[nf][0], s[nf][1]));
            rm1 = fmaxf(rm1, fmaxf(s[nf][2], s[nf][3]));
        }
        rm0 = fmaxf(rm0, __shfl_xor_sync(0xffffffffu, rm0, 1));
        rm0 = fmaxf(rm0, __shfl_xor_sync(0xffffffffu, rm0, 2));
        rm1 = fmaxf(rm1, __shfl_xor_sync(0xffffffffu, rm1, 1));
        rm1 = fmaxf(rm1, __shfl_xor_sync(0xffffffffu, rm1, 2));

        const float mn0 = fmaxf(m0, rm0), mn1 = fmaxf(m1, rm1);
        const float sc0 = fexp2(m0 - mn0), sc1 = fexp2(m1 - mn1);
        m0 = mn0; m1 = mn1;

        float rs0 = 0.f, rs1 = 0.f;
#pragma unroll
        for (int nf = 0; nf < 8; nf++) {
            s[nf][0] = fexp2(s[nf][0] - mn0);
            s[nf][1] = fexp2(s[nf][1] - mn0);
            s[nf][2] = fexp2(s[nf][2] - mn1);
            s[nf][3] = fexp2(s[nf][3] - mn1);
            rs0 += s[nf][0] + s[nf][1];
            rs1 += s[nf][2] + s[nf][3];
        }
        rs0 += __shfl_xor_sync(0xffffffffu, rs0, 1);
        rs0 += __shfl_xor_sync(0xffffffffu, rs0, 2);
        rs1 += __shfl_xor_sync(0xffffffffu, rs1, 1);
        rs1 += __shfl_xor_sync(0xffffffffu, rs1, 2);
        l0 = l0 * sc0 + rs0;
        l1 = l1 * sc1 + rs1;

#pragma unroll
        for (int nf = 0; nf < 16; nf++) {
            o[nf][0] *= sc0; o[nf][1] *= sc0;
            o[nf][2] *= sc1; o[nf][3] *= sc1;
        }

        // ---- write P hi/lo to smem (own warp rows only) ----
        {
            const int pr0 = w * 16 + g;
#pragma unroll
            for (int nf = 0; nf < 8; nf++) {
                const int pc = nf * 8 + tig * 2;
                __nv_bfloat16 h0 = __float2bfloat16(s[nf][0]);
                __nv_bfloat16 h1 = __float2bfloat16(s[nf][1]);
                *(__nv_bfloat162*)(sb + O_PH + pr0 * PP + pc) = __halves2bfloat162(h0, h1);
                *(__nv_bfloat162*)(sb + O_PL + pr0 * PP + pc) = __halves2bfloat162(
                    __float2bfloat16(s[nf][0] - __bfloat162float(h0)),
                    __float2bfloat16(s[nf][1] - __bfloat162float(h1)));
                h0 = __float2bfloat16(s[nf][2]);
                h1 = __float2bfloat16(s[nf][3]);
                *(__nv_bfloat162*)(sb + O_PH + (pr0 + 8) * PP + pc) = __halves2bfloat162(h0, h1);
                *(__nv_bfloat162*)(sb + O_PL + (pr0 + 8) * PP + pc) = __halves2bfloat162(
                    __float2bfloat16(s[nf][2] - __bfloat162float(h0)),
                    __float2bfloat16(s[nf][3] - __bfloat162float(h1)));
            }
        }
        __syncwarp();

        // ---- O += P V  (16 x 128 per warp) ----
#pragma unroll
        for (int ks2 = 0; ks2 < 4; ks2++) {
            uint32_t ph4[4], pl4[4];
            const uint32_t pd = smb + (uint32_t)(O_PH + prow * PP + ks2 * 16 + pcol8) * 2;
            ldsm4(ph4, pd);
            ldsm4(pl4, pd + (uint32_t)(128 * PP) * 2);
#pragma unroll
            for (int nfp = 0; nfp < 8; nfp++) {
                uint32_t vh4[4], vl4[4];
                const uint32_t vd = smb + (uint32_t)(O_VH + (vrow + ks2 * 16) * QP + nfp * 16 + vcol8) * 2;
                ldsm4t(vh4, vd);
                ldsm4t(vl4, vd + (uint32_t)(64 * QP) * 2);
                mma16816(o[2 * nfp],     ph4, vh4[0], vh4[1]);
                mma16816(o[2 * nfp],     ph4, vl4[0], vl4[1]);
                mma16816(o[2 * nfp],     pl4, vh4[0], vh4[1]);
                mma16816(o[2 * nfp + 1], ph4, vh4[2], vh4[3]);
                mma16816(o[2 * nfp + 1], ph4, vl4[2], vl4[3]);
                mma16816(o[2 * nfp + 1], pl4, vh4[2], vh4[3]);
            }
        }
    }

    // ---- epilogue: normalize + hi/lo split + store ----
    const float inv0 = 1.f / l0, inv1 = 1.f / l1;
    const long gr0 = rowbase + w * 16 + g;
#pragma unroll
    for (int nf = 0; nf < 16; nf++) {
        const long gc = colbase + nf * 8 + tig * 2;
        float v0 = o[nf][0] * inv0, v1 = o[nf][1] * inv0;
        __nv_bfloat16 h0 = __float2bfloat16(v0), h1 = __float2bfloat16(v1);
        *(__nv_bfloat162*)(Ohi + gr0 * DIM + gc) = __halves2bfloat162(h0, h1);
        *(__nv_bfloat162*)(Olo + gr0 * DIM + gc) = __halves2bfloat162(
            __float2bfloat16(v0 - __bfloat162float(h0)),
            __float2bfloat16(v1 - __bfloat162float(h1)));
        v0 = o[nf][2] * inv1; v1 = o[nf][3] * inv1;
        h0 = __float2bfloat16(v0); h1 = __float2bfloat16(v1);
        *(__nv_bfloat162*)(Ohi + (gr0 + 8) * DIM + gc) = __halves2bfloat162(h0, h1);
        *(__nv_bfloat162*)(Olo + (gr0 + 8) * DIM + gc) = __halves2bfloat162(
            __float2bfloat16(v0 - __bfloat162float(h0)),
            __float2bfloat16(v1 - __bfloat162float(h1)));
    }
}

// ---------------------------------------------------------------------------
// Launch
// ---------------------------------------------------------------------------
extern "C" void kernel_launch(void* const* d_in, const int* in_sizes, int n_in,
                              void* d_out, int out_size)
{
    const float* x    = (const float*)d_in[0];
    const float* fcos = (const float*)d_in[2];
    const float* fsin = (const float*)d_in[3];
    const float* wq   = (const float*)d_in[5];
    const float* wk   = (const float*)d_in[6];
    const float* wv   = (const float*)d_in[7];
    const float* wo   = (const float*)d_in[8];
    float* out = (float*)d_out;

    float *xq, *xk, *xv;
    __nv_bfloat16 *ahi, *alo, *bhi, *blo, *qh, *ql, *kh, *kl, *vh, *vl;
    cudaGetSymbolAddress((void**)&xq,  g_xq);
    cudaGetSymbolAddress((void**)&xk,  g_xk);
    cudaGetSymbolAddress((void**)&xv,  g_xv);
    cudaGetSymbolAddress((void**)&ahi, g_ahi);
    cudaGetSymbolAddress((void**)&alo, g_alo);
    cudaGetSymbolAddress((void**)&bhi, g_bhi);
    cudaGetSymbolAddress((void**)&blo, g_blo);
    cudaGetSymbolAddress((void**)&qh,  g_qhi);
    cudaGetSymbolAddress((void**)&ql,  g_qlo);
    cudaGetSymbolAddress((void**)&kh,  g_khi);
    cudaGetSymbolAddress((void**)&kl,  g_klo);
    cudaGetSymbolAddress((void**)&vh,  g_vhi);
    cudaGetSymbolAddress((void**)&vl,  g_vlo);

    cudaFuncSetAttribute(tc_gemm, cudaFuncAttributeMaxDynamicSharedMemorySize, GEMM_SMEM);
    cudaFuncSetAttribute(attn_mma, cudaFuncAttributeMaxDynamicSharedMemorySize, ATTN_SMEM);

    const int cvt_blocks = (MM * DIM) / (256 * 4);           // 16384
    const int gemm_grid  = (MM / BM) * (DIM / BN);           // 512

    cvt_hilo<<<cvt_blocks, 256>>>(x, ahi, alo);
    cvt_hilo<<<cvt_blocks, 256>>>(wq, bhi, blo);
    tc_gemm<<<gemm_grid, 256, GEMM_SMEM>>>(ahi, alo, bhi, blo, xq);
    cvt_hilo<<<cvt_blocks, 256>>>(wk, bhi, blo);
    tc_gemm<<<gemm_grid, 256, GEMM_SMEM>>>(ahi, alo, bhi, blo, xk);
    cvt_hilo<<<cvt_blocks, 256>>>(wv, bhi, blo);
    tc_gemm<<<gemm_grid, 256, GEMM_SMEM>>>(ahi, alo, bhi, blo, xv);

    const int npairs = MM * (DIM / 2);
    rope_cvt<<<npairs / 256, 256>>>(xq, xk, xv, fcos, fsin, qh, ql, kh, kl, vh, vl);

    attn_mma<<<dim3(Sq / 128, Bz * Hh), 256, ATTN_SMEM>>>(qh, ql, kh, kl, vh, vl, ahi, alo);

    cvt_hilo<<<cvt_blocks, 256>>>(wo, bhi, blo);
    tc_gemm<<<gemm_grid, 256, GEMM_SMEM>>>(ahi, alo, bhi, blo, out);
}

// round 6
// speedup vs baseline: 5.7351x; 2.4607x over previous
#include <cuda_runtime.h>
#include <cuda_bf16.h>
#include <cuda_fp16.h>
#include <cstdint>
#include <math.h>

// Problem constants
constexpr int Bz  = 4;
constexpr int Sq  = 1024;
constexpr int DIM = 4096;
constexpr int Hh  = 32;
constexpr int HD  = 128;
constexpr int MM  = Bz * Sq;        // 4096 rows
constexpr float QS2 = 0.08838834764831845f * 1.4426950408889634f; // 1/sqrt(128)*log2(e)

// Scratch (static device globals)
__device__ float g_xq[MM * DIM];
__device__ float g_xk[MM * DIM];
__device__ float g_xv[MM * DIM];
__device__ __half g_xh[MM * DIM];        // fp16 activations for GEMM
__device__ __half g_wh[DIM * DIM];       // fp16 weights for GEMM
__device__ __half g_atth[MM * DIM];      // fp16 attention output
__device__ __nv_bfloat16 g_qhi[MM * DIM];
__device__ __nv_bfloat16 g_qlo[MM * DIM];
__device__ __nv_bfloat16 g_khi[MM * DIM];
__device__ __nv_bfloat16 g_klo[MM * DIM];
__device__ __nv_bfloat16 g_vhi[MM * DIM];
__device__ __nv_bfloat16 g_vlo[MM * DIM];

// ---------------------------------------------------------------------------
// helpers
// ---------------------------------------------------------------------------
__device__ __forceinline__ uint32_t smem_u32(const void* p) {
    uint32_t a;
    asm("{ .reg .u64 t; cvta.to.shared.u64 t, %1; cvt.u32.u64 %0, t; }"
        : "=r"(a) : "l"(p));
    return a;
}
__device__ __forceinline__ void ldsm4(uint32_t* r, uint32_t addr) {
    asm volatile("ldmatrix.sync.aligned.m8n8.x4.shared.b16 {%0,%1,%2,%3}, [%4];"
        : "=r"(r[0]), "=r"(r[1]), "=r"(r[2]), "=r"(r[3]) : "r"(addr));
}
__device__ __forceinline__ void ldsm4t(uint32_t* r, uint32_t addr) {
    asm volatile("ldmatrix.sync.aligned.m8n8.x4.trans.shared.b16 {%0,%1,%2,%3}, [%4];"
        : "=r"(r[0]), "=r"(r[1]), "=r"(r[2]), "=r"(r[3]) : "r"(addr));
}
__device__ __forceinline__ void mma_bf16(float* d, const uint32_t* a,
                                         uint32_t b0, uint32_t b1) {
    asm volatile(
        "mma.sync.aligned.m16n8k16.row.col.f32.bf16.bf16.f32 "
        "{%0,%1,%2,%3}, {%4,%5,%6,%7}, {%8,%9}, {%0,%1,%2,%3};"
        : "+f"(d[0]), "+f"(d[1]), "+f"(d[2]), "+f"(d[3])
        : "r"(a[0]), "r"(a[1]), "r"(a[2]), "r"(a[3]), "r"(b0), "r"(b1));
}
__device__ __forceinline__ void mma_f16(float* d, const uint32_t* a,
                                        uint32_t b0, uint32_t b1) {
    asm volatile(
        "mma.sync.aligned.m16n8k16.row.col.f32.f16.f16.f32 "
        "{%0,%1,%2,%3}, {%4,%5,%6,%7}, {%8,%9}, {%0,%1,%2,%3};"
        : "+f"(d[0]), "+f"(d[1]), "+f"(d[2]), "+f"(d[3])
        : "r"(a[0]), "r"(a[1]), "r"(a[2]), "r"(a[3]), "r"(b0), "r"(b1));
}
__device__ __forceinline__ float fexp2(float x) {
    float y;
    asm("ex2.approx.ftz.f32 %0, %1;" : "=f"(y) : "f"(x));
    return y;
}

// ---------------------------------------------------------------------------
// fp32 -> fp16 conversion, 4 elems per thread.
// ---------------------------------------------------------------------------
__global__ __launch_bounds__(256)
void cvt_h(const float* __restrict__ s, __half* __restrict__ d)
{
    const long i = ((long)blockIdx.x * 256 + threadIdx.x) * 4;
    float4 v = *(const float4*)(s + i);
    *(__half2*)(d + i)     = __floats2half2_rn(v.x, v.y);
    *(__half2*)(d + i + 2) = __floats2half2_rn(v.z, v.w);
}

// ---------------------------------------------------------------------------
// Single-pass fp16 GEMM:  C[4096,4096] = A * W^T (both K-major fp16).
// CTA 128x128, BK=32, 8 warps (2m x 4n), warp tile 64x32, ldmatrix.x4,
// 4-stage cp.async, 2 CTAs/SM.  KPAD=40 -> conflict-free.
// ---------------------------------------------------------------------------
constexpr int BM = 128, BN = 128, BK = 32, KPAD = 40;
constexpr int A_E = BM * KPAD;                 // 5120
constexpr int B_E = BN * KPAD;                 // 5120
constexpr int STAGE_E = A_E + B_E;             // 10240 elems = 20KB
constexpr int STAGES = 4;
constexpr int GEMM_SMEM = STAGES * STAGE_E * 2;  // 81920 bytes

__global__ __launch_bounds__(256, 2)
void tc_gemm_h(const __half* __restrict__ A, const __half* __restrict__ W,
               float* __restrict__ C)
{
    extern __shared__ __align__(16) __half sh[];
    const uint32_t smb = smem_u32(sh);

    const int tid  = threadIdx.x;
    const int wid  = tid >> 5;
    const int lane = tid & 31;
    const int g    = lane >> 2;
    const int tig  = lane & 3;
    const int warp_m = wid & 1;    // 0..1 (64 rows)
    const int warp_n = wid >> 1;   // 0..3 (32 cols)

    // raster: groups of 4 m-tiles sweep 32 n-tiles
    const int bid = blockIdx.x;
    const int grp = bid >> 7;
    const int r   = bid & 127;
    const int m0  = (grp * 4 + (r & 3)) * BM;
    const int n0  = (r >> 2) * BN;

    const __half* Ag = A + (long)m0 * DIM;
    const __half* Wg = W + (long)n0 * DIM;

    // copy map: 512 uint4 per tile; row = c>>2, col = (c&3)*8
    auto issue = [&](int kt, int st) {
        const long kof = (long)kt * BK;
        const uint32_t sbase = smb + (uint32_t)(st * STAGE_E) * 2;
#pragma unroll
        for (int q = 0; q < 2; q++) {
            const int c = tid + 256 * q;
            const int row = c >> 2, cc = (c & 3) * 8;
            const __half* s = Ag + (long)row * DIM + kof + cc;
            const uint32_t d = sbase + (uint32_t)(row * KPAD + cc) * 2;
            asm volatile("cp.async.cg.shared.global [%0], [%1], 16;" :: "r"(d), "l"(s));
        }
#pragma unroll
        for (int q = 0; q < 2; q++) {
            const int c = tid + 256 * q;
            const int row = c >> 2, cc = (c & 3) * 8;
            const __half* s = Wg + (long)row * DIM + kof + cc;
            const uint32_t d = sbase + (uint32_t)(A_E + row * KPAD + cc) * 2;
            asm volatile("cp.async.cg.shared.global [%0], [%1], 16;" :: "r"(d), "l"(s));
        }
    };

    float acc[4][4][4];
#pragma unroll
    for (int i = 0; i < 4; i++)
#pragma unroll
        for (int j = 0; j < 4; j++)
#pragma unroll
            for (int q = 0; q < 4; q++) acc[i][j][q] = 0.f;

    issue(0, 0); asm volatile("cp.async.commit_group;" ::: "memory");
    issue(1, 1); asm volatile("cp.async.commit_group;" ::: "memory");
    issue(2, 2); asm volatile("cp.async.commit_group;" ::: "memory");

    const int arow  = warp_m * 64 + (lane & 15);
    const int acol8 = (lane >> 4) << 3;
    const int brow  = warp_n * 32 + (lane & 7) + ((lane >> 4) << 3);
    const int bcol8 = ((lane >> 3) & 1) << 3;

    const int NT = DIM / BK;   // 128
    for (int t = 0; t < NT; t++) {
        asm volatile("cp.async.wait_group 2;" ::: "memory");
        __syncthreads();

        if (t + 3 < NT) issue(t + 3, (t + 3) & 3);
        asm volatile("cp.async.commit_group;" ::: "memory");

        const uint32_t base = smb + (uint32_t)((t & 3) * STAGE_E) * 2;

#pragma unroll
        for (int ks = 0; ks < 2; ks++) {
            const int kk = ks * 16;
            uint32_t af[4][4], bf[2][4];
#pragma unroll
            for (int mf = 0; mf < 4; mf++)
                ldsm4(af[mf], base + (uint32_t)((arow + mf * 16) * KPAD + kk + acol8) * 2);
#pragma unroll
            for (int nfp = 0; nfp < 2; nfp++)
                ldsm4(bf[nfp], base + (uint32_t)(A_E + (brow + nfp * 16) * KPAD + kk + bcol8) * 2);
#pragma unroll
            for (int mf = 0; mf < 4; mf++)
#pragma unroll
                for (int nfp = 0; nfp < 2; nfp++) {
                    mma_f16(acc[mf][2 * nfp],     af[mf], bf[nfp][0], bf[nfp][1]);
                    mma_f16(acc[mf][2 * nfp + 1], af[mf], bf[nfp][2], bf[nfp][3]);
                }
        }
        __syncthreads();
    }

    // epilogue
#pragma unroll
    for (int mf = 0; mf < 4; mf++) {
        const long gr0 = m0 + warp_m * 64 + mf * 16 + g;
#pragma unroll
        for (int nf = 0; nf < 4; nf++) {
            const int gc = n0 + warp_n * 32 + nf * 8 + tig * 2;
            *(float2*)(C + gr0 * DIM + gc)       = make_float2(acc[mf][nf][0], acc[mf][nf][1]);
            *(float2*)(C + (gr0 + 8) * DIM + gc) = make_float2(acc[mf][nf][2], acc[mf][nf][3]);
        }
    }
}

// ---------------------------------------------------------------------------
// RoPE + hi/lo bf16 split for attention inputs.
// ---------------------------------------------------------------------------
__global__ __launch_bounds__(256)
void rope_cvt(const float* __restrict__ q, const float* __restrict__ k,
              const float* __restrict__ v,
              const float* __restrict__ fcos, const float* __restrict__ fsin,
              __nv_bfloat16* __restrict__ qh, __nv_bfloat16* __restrict__ ql,
              __nv_bfloat16* __restrict__ kh, __nv_bfloat16* __restrict__ kl,
              __nv_bfloat16* __restrict__ vh, __nv_bfloat16* __restrict__ vl)
{
    const int idx = blockIdx.x * blockDim.x + threadIdx.x;
    constexpr int PAIRS_PER_ROW = DIM / 2;
    const int row = idx / PAIRS_PER_ROW;
    const int pr  = idx - row * PAIRS_PER_ROW;
    const int s = row & (Sq - 1);
    const int p = pr & 63;
    const float c  = fcos[s * 64 + p];
    const float sn = fsin[s * 64 + p];
    const long off = (long)row * DIM + 2 * pr;

    float2 qa = *(const float2*)(q + off);
    float qx = (qa.x * c - qa.y * sn) * QS2;
    float qy = (qa.x * sn + qa.y * c) * QS2;
    __nv_bfloat16 h0 = __float2bfloat16(qx), h1 = __float2bfloat16(qy);
    *(__nv_bfloat162*)(qh + off) = __halves2bfloat162(h0, h1);
    *(__nv_bfloat162*)(ql + off) = __halves2bfloat162(
        __float2bfloat16(qx - __bfloat162float(h0)),
        __float2bfloat16(qy - __bfloat162float(h1)));

    float2 ka = *(const float2*)(k + off);
    float kx = ka.x * c - ka.y * sn;
    float ky = ka.x * sn + ka.y * c;
    h0 = __float2bfloat16(kx); h1 = __float2bfloat16(ky);
    *(__nv_bfloat162*)(kh + off) = __halves2bfloat162(h0, h1);
    *(__nv_bfloat162*)(kl + off) = __halves2bfloat162(
        __float2bfloat16(kx - __bfloat162float(h0)),
        __float2bfloat16(ky - __bfloat162float(h1)));

    float2 va = *(const float2*)(v + off);
    h0 = __float2bfloat16(va.x); h1 = __float2bfloat16(va.y);
    *(__nv_bfloat162*)(vh + off) = __halves2bfloat162(h0, h1);
    *(__nv_bfloat162*)(vl + off) = __halves2bfloat162(
        __float2bfloat16(va.x - __bfloat162float(h0)),
        __float2bfloat16(va.y - __bfloat162float(h1)));
}

// ---------------------------------------------------------------------------
// Flash attention (bf16 hi/lo 3-split, tensor cores).  Q block 128, KV 64.
// Output written as single fp16 (consumed by fp16 wo GEMM).
// ---------------------------------------------------------------------------
constexpr int QP = 136;
constexpr int PP = 72;
constexpr int O_QH = 0;
constexpr int O_QL = O_QH + 128 * QP;
constexpr int O_KH = O_QL + 128 * QP;
constexpr int O_KL = O_KH + 64 * QP;
constexpr int O_VH = O_KL + 64 * QP;
constexpr int O_VL = O_VH + 64 * QP;
constexpr int O_PH = O_VL + 64 * QP;
constexpr int O_PL = O_PH + 128 * PP;
constexpr int ATTN_SMEM = (O_PL + 128 * PP) * 2;

__global__ __launch_bounds__(256, 1)
void attn_mma(const __nv_bfloat16* __restrict__ Qh, const __nv_bfloat16* __restrict__ Ql,
              const __nv_bfloat16* __restrict__ Kh, const __nv_bfloat16* __restrict__ Kl,
              const __nv_bfloat16* __restrict__ Vh, const __nv_bfloat16* __restrict__ Vl,
              __half* __restrict__ Oh)
{
    extern __shared__ __align__(16) __nv_bfloat16 sb[];
    const uint32_t smb = smem_u32(sb);

    const int tid  = threadIdx.x;
    const int w    = tid >> 5;
    const int lane = tid & 31;
    const int g    = lane >> 2;
    const int tig  = lane & 3;

    const int qb = blockIdx.x;
    const int bh = blockIdx.y;
    const int b  = bh >> 5;
    const int h  = bh & (Hh - 1);
    const int rowbase = b * Sq + qb * 128;
    const long colbase = h * HD;

    {
        const __nv_bfloat16* srcs[2] = { Qh, Ql };
        const uint32_t dsts[2] = { O_QH, O_QL };
#pragma unroll
        for (int a2 = 0; a2 < 2; a2++)
#pragma unroll
            for (int q = 0; q < 8; q++) {
                const int u = tid + 256 * q;
                const int rr = u >> 4, c8 = (u & 15) * 8;
                uint4 v = *(const uint4*)(srcs[a2] + (long)(rowbase + rr) * DIM + colbase + c8);
                *(uint4*)(sb + dsts[a2] + rr * QP + c8) = v;
            }
    }
    __syncthreads();

    uint32_t qfh[8][4], qfl[8][4];
    {
        const int rowQ = w * 16 + (lane & 15);
        const int colH = (lane >> 4) << 3;
#pragma unroll
        for (int ks = 0; ks < 8; ks++) {
            const uint32_t ad = smb + (uint32_t)(O_QH + rowQ * QP + ks * 16 + colH) * 2;
            ldsm4(qfh[ks], ad);
            ldsm4(qfl[ks], ad + (uint32_t)(128 * QP) * 2);
        }
    }

    float o[16][4];
#pragma unroll
    for (int i = 0; i < 16; i++)
#pragma unroll
        for (int q = 0; q < 4; q++) o[i][q] = 0.f;
    float m0 = -1e30f, m1 = -1e30f, l0 = 0.f, l1 = 0.f;

    const int browK = (lane & 7) + ((lane >> 4) << 3);
    const int bcol8 = ((lane >> 3) & 1) << 3;
    const int vrow  = (lane & 7) + (((lane >> 3) & 1) << 3);
    const int vcol8 = (lane >> 4) << 3;
    const int prow  = w * 16 + (lane & 15);
    const int pcol8 = (lane >> 4) << 3;

    const int nkb = 2 * qb + 2;
    for (int kb = 0; kb < nkb; kb++) {
        __syncthreads();

        {
            const __nv_bfloat16* srcs[4] = { Kh, Kl, Vh, Vl };
            const uint32_t dsts[4] = { O_KH, O_KL, O_VH, O_VL };
            const long rbase = (long)(b * Sq + kb * 64);
#pragma unroll
            for (int a2 = 0; a2 < 4; a2++)
#pragma unroll
                for (int q = 0; q < 4; q++) {
                    const int u = tid + 256 * q;
                    const int rr = u >> 4, c8 = (u & 15) * 8;
                    uint4 v = *(const uint4*)(srcs[a2] + (rbase + rr) * DIM + colbase + c8);
                    *(uint4*)(sb + dsts[a2] + rr * QP + c8) = v;
                }
        }
        __syncthreads();

        float s[8][4];
#pragma unroll
        for (int i = 0; i < 8; i++)
#pragma unroll
            for (int q = 0; q < 4; q++) s[i][q] = 0.f;

#pragma unroll
        for (int ks = 0; ks < 8; ks++) {
#pragma unroll
            for (int nfp = 0; nfp < 4; nfp++) {
                uint32_t bh4[4], bl4[4];
                const uint32_t bd = smb + (uint32_t)(O_KH + (browK + nfp * 16) * QP + ks * 16 + bcol8) * 2;
                ldsm4(bh4, bd);
                ldsm4(bl4, bd + (uint32_t)(64 * QP) * 2);
                mma_bf16(s[2 * nfp],     qfh[ks], bh4[0], bh4[1]);
                mma_bf16(s[2 * nfp],     qfh[ks], bl4[0], bl4[1]);
                mma_bf16(s[2 * nfp],     qfl[ks], bh4[0], bh4[1]);
                mma_bf16(s[2 * nfp + 1], qfh[ks], bh4[2], bh4[3]);
                mma_bf16(s[2 * nfp + 1], qfh[ks], bl4[2], bl4[3]);
                mma_bf16(s[2 * nfp + 1], qfl[ks], bh4[2], bh4[3]);
            }
        }

        const int r0g = qb * 128 + w * 16 + g;
        if (kb * 64 + 63 > r0g) {
            const int r1g = r0g + 8;
#pragma unroll
            for (int nf = 0; nf < 8; nf++) {
                const int c0 = kb * 64 + nf * 8 + tig * 2;
                if (c0 > r0g)     s[nf][0] = -1e30f;
                if (c0 + 1 > r0g) s[nf][1] = -1e30f;
                if (c0 > r1g)     s[nf][2] = -1e30f;
                if (c0 + 1 > r1g) s[nf][3] = -1e30f;
            }
        }

        float rm0 = -1e30f, rm1 = -1e30f;
#pragma unroll
        for (int nf = 0; nf < 8; nf++) {
            rm0 = fmaxf(rm0, fmaxf(s[nf][0], s[nf][1]));
            rm1 = fmaxf(rm1, fmaxf(s[nf][2], s[nf][3]));
        }
        rm0 = fmaxf(rm0, __shfl_xor_sync(0xffffffffu, rm0, 1));
        rm0 = fmaxf(rm0, __shfl_xor_sync(0xffffffffu, rm0, 2));
        rm1 = fmaxf(rm1, __shfl_xor_sync(0xffffffffu, rm1, 1));
        rm1 = fmaxf(rm1, __shfl_xor_sync(0xffffffffu, rm1, 2));

        const float mn0 = fmaxf(m0, rm0), mn1 = fmaxf(m1, rm1);
        const float sc0 = fexp2(m0 - mn0), sc1 = fexp2(m1 - mn1);
        m0 = mn0; m1 = mn1;

        float rs0 = 0.f, rs1 = 0.f;
#pragma unroll
        for (int nf = 0; nf < 8; nf++) {
            s[nf][0] = fexp2(s[nf][0] - mn0);
            s[nf][1] = fexp2(s[nf][1] - mn0);
            s[nf][2] = fexp2(s[nf][2] - mn1);
            s[nf][3] = fexp2(s[nf][3] - mn1);
            rs0 += s[nf][0] + s[nf][1];
            rs1 += s[nf][2] + s[nf][3];
        }
        rs0 += __shfl_xor_sync(0xffffffffu, rs0, 1);
        rs0 += __shfl_xor_sync(0xffffffffu, rs0, 2);
        rs1 += __shfl_xor_sync(0xffffffffu, rs1, 1);
        rs1 += __shfl_xor_sync(0xffffffffu, rs1, 2);
        l0 = l0 * sc0 + rs0;
        l1 = l1 * sc1 + rs1;

#pragma unroll
        for (int nf = 0; nf < 16; nf++) {
            o[nf][0] *= sc0; o[nf][1] *= sc0;
            o[nf][2] *= sc1; o[nf][3] *= sc1;
        }

        {
            const int pr0 = w * 16 + g;
#pragma unroll
            for (int nf = 0; nf < 8; nf++) {
                const int pc = nf * 8 + tig * 2;
                __nv_bfloat16 h0 = __float2bfloat16(s[nf][0]);
                __nv_bfloat16 h1 = __float2bfloat16(s[nf][1]);
                *(__nv_bfloat162*)(sb + O_PH + pr0 * PP + pc) = __halves2bfloat162(h0, h1);
                *(__nv_bfloat162*)(sb + O_PL + pr0 * PP + pc) = __halves2bfloat162(
                    __float2bfloat16(s[nf][0] - __bfloat162float(h0)),
                    __float2bfloat16(s[nf][1] - __bfloat162float(h1)));
                h0 = __float2bfloat16(s[nf][2]);
                h1 = __float2bfloat16(s[nf][3]);
                *(__nv_bfloat162*)(sb + O_PH + (pr0 + 8) * PP + pc) = __halves2bfloat162(h0, h1);
                *(__nv_bfloat162*)(sb + O_PL + (pr0 + 8) * PP + pc) = __halves2bfloat162(
                    __float2bfloat16(s[nf][2] - __bfloat162float(h0)),
                    __float2bfloat16(s[nf][3] - __bfloat162float(h1)));
            }
        }
        __syncwarp();

#pragma unroll
        for (int ks2 = 0; ks2 < 4; ks2++) {
            uint32_t ph4[4], pl4[4];
            const uint32_t pd = smb + (uint32_t)(O_PH + prow * PP + ks2 * 16 + pcol8) * 2;
            ldsm4(ph4, pd);
            ldsm4(pl4, pd + (uint32_t)(128 * PP) * 2);
#pragma unroll
            for (int nfp = 0; nfp < 8; nfp++) {
                uint32_t vh4[4], vl4[4];
                const uint32_t vd = smb + (uint32_t)(O_VH + (vrow + ks2 * 16) * QP + nfp * 16 + vcol8) * 2;
                ldsm4t(vh4, vd);
                ldsm4t(vl4, vd + (uint32_t)(64 * QP) * 2);
                mma_bf16(o[2 * nfp],     ph4, vh4[0], vh4[1]);
                mma_bf16(o[2 * nfp],     ph4, vl4[0], vl4[1]);
                mma_bf16(o[2 * nfp],     pl4, vh4[0], vh4[1]);
                mma_bf16(o[2 * nfp + 1], ph4, vh4[2], vh4[3]);
                mma_bf16(o[2 * nfp + 1], ph4, vl4[2], vl4[3]);
                mma_bf16(o[2 * nfp + 1], pl4, vh4[2], vh4[3]);
            }
        }
    }

    // epilogue: normalize + store fp16
    const float inv0 = 1.f / l0, inv1 = 1.f / l1;
    const long gr0 = rowbase + w * 16 + g;
#pragma unroll
    for (int nf = 0; nf < 16; nf++) {
        const long gc = colbase + nf * 8 + tig * 2;
        *(__half2*)(Oh + gr0 * DIM + gc) =
            __floats2half2_rn(o[nf][0] * inv0, o[nf][1] * inv0);
        *(__half2*)(Oh + (gr0 + 8) * DIM + gc) =
            __floats2half2_rn(o[nf][2] * inv1, o[nf][3] * inv1);
    }
}

// ---------------------------------------------------------------------------
// Launch
// ---------------------------------------------------------------------------
extern "C" void kernel_launch(void* const* d_in, const int* in_sizes, int n_in,
                              void* d_out, int out_size)
{
    const float* x    = (const float*)d_in[0];
    const float* fcos = (const float*)d_in[2];
    const float* fsin = (const float*)d_in[3];
    const float* wq   = (const float*)d_in[5];
    const float* wk   = (const float*)d_in[6];
    const float* wv   = (const float*)d_in[7];
    const float* wo   = (const float*)d_in[8];
    float* out = (float*)d_out;

    float *xq, *xk, *xv;
    __half *xh, *wh, *atth;
    __nv_bfloat16 *qh, *ql, *kh, *kl, *vh, *vl;
    cudaGetSymbolAddress((void**)&xq,  g_xq);
    cudaGetSymbolAddress((void**)&xk,  g_xk);
    cudaGetSymbolAddress((void**)&xv,  g_xv);
    cudaGetSymbolAddress((void**)&xh,  g_xh);
    cudaGetSymbolAddress((void**)&wh,  g_wh);
    cudaGetSymbolAddress((void**)&atth, g_atth);
    cudaGetSymbolAddress((void**)&qh,  g_qhi);
    cudaGetSymbolAddress((void**)&ql,  g_qlo);
    cudaGetSymbolAddress((void**)&kh,  g_khi);
    cudaGetSymbolAddress((void**)&kl,  g_klo);
    cudaGetSymbolAddress((void**)&vh,  g_vhi);
    cudaGetSymbolAddress((void**)&vl,  g_vlo);

    cudaFuncSetAttribute(tc_gemm_h, cudaFuncAttributeMaxDynamicSharedMemorySize, GEMM_SMEM);
    cudaFuncSetAttribute(attn_mma, cudaFuncAttributeMaxDynamicSharedMemorySize, ATTN_SMEM);

    const int cvt_blocks = (MM * DIM) / (256 * 4);           // 16384
    const int gemm_grid  = (MM / BM) * (DIM / BN);           // 1024

    cvt_h<<<cvt_blocks, 256>>>(x, xh);
    cvt_h<<<cvt_blocks, 256>>>(wq, wh);
    tc_gemm_h<<<gemm_grid, 256, GEMM_SMEM>>>(xh, wh, xq);
    cvt_h<<<cvt_blocks, 256>>>(wk, wh);
    tc_gemm_h<<<gemm_grid, 256, GEMM_SMEM>>>(xh, wh, xk);
    cvt_h<<<cvt_blocks, 256>>>(wv, wh);
    tc_gemm_h<<<gemm_grid, 256, GEMM_SMEM>>>(xh, wh, xv);

    const int npairs = MM * (DIM / 2);
    rope_cvt<<<npairs / 256, 256>>>(xq, xk, xv, fcos, fsin, qh, ql, kh, kl, vh, vl);

    attn_mma<<<dim3(Sq / 128, Bz * Hh), 256, ATTN_SMEM>>>(qh, ql, kh, kl, vh, vl, atth);

    cvt_h<<<cvt_blocks, 256>>>(wo, wh);
    tc_gemm_h<<<gemm_grid, 256, GEMM_SMEM>>>(atth, wh, out);
}